// round 4
// baseline (speedup 1.0000x reference)
#include <cuda_runtime.h>
#include <stdint.h>

#define TOKENS 16384
#define KDIM   2048
#define EDIM   64
#define TOPK   8
#define BM     128
#define BK     32
#define NKT    (KDIM / BK)   // 64 k-tiles
#define AST    36            // A smem row stride (floats): banks 4g+c -> conflict-free frags
#define BST    37            // B smem row stride (floats): banks 5n+k -> conflict-free staging
#define SCST   66            // epilogue score row stride

// smem: A[128][36] f32 @0 (18432B), B[64][37] f32 @18432 (9472B) -> 27904B
// epilogue aliases whole region as scores: 128*66*4 = 33792B
#define SMEM_BYTES 33792

__device__ __forceinline__ float tf32r(float v) {
    uint32_t u;
    asm("cvt.rna.tf32.f32 %0, %1;" : "=r"(u) : "f"(v));
    return __uint_as_float(u);
}

__device__ __forceinline__ void mma_tf32(float c[4],
                                         float a0, float a1, float a2, float a3,
                                         float b0, float b1) {
    uint32_t A0 = __float_as_uint(a0), A1 = __float_as_uint(a1);
    uint32_t A2 = __float_as_uint(a2), A3 = __float_as_uint(a3);
    uint32_t B0 = __float_as_uint(b0), B1 = __float_as_uint(b1);
    asm volatile(
        "mma.sync.aligned.m16n8k8.row.col.f32.tf32.tf32.f32 "
        "{%0,%1,%2,%3},{%4,%5,%6,%7},{%8,%9},{%0,%1,%2,%3};\n"
        : "+f"(c[0]), "+f"(c[1]), "+f"(c[2]), "+f"(c[3])
        : "r"(A0), "r"(A1), "r"(A2), "r"(A3), "r"(B0), "r"(B1));
}

__global__ void __launch_bounds__(256, 1)
router_kernel(const float* __restrict__ X, const float* __restrict__ W,
              const float* __restrict__ bias, float* __restrict__ out)
{
    extern __shared__ char smem[];
    float* As = (float*)smem;                 // [128][AST]
    float* Bs = (float*)(smem + 18432);       // [64][BST]  (Bt[n][k])
    float* sc = (float*)smem;                 // epilogue alias

    const int tid  = threadIdx.x;
    const int warp = tid >> 5;
    const int lane = tid & 31;
    const int mb   = blockIdx.x * BM;

    const int g  = lane >> 2;         // 0..7
    const int c  = lane & 3;          // k offset within chunk
    const int t2 = (lane & 3) << 1;   // C-fragment column offset
    const int arow = warp << 4;       // warp's 16-token slice

    // staging decomposition
    const int arg = tid >> 3;         // A row group 0..31
    const int akb = (tid & 7) << 2;   // A k base 0,4,...,28
    const int bn  = tid & 63;         // B: expert column 0..63
    const int bkg = (tid >> 6) << 3;  // B: k group base 0,8,16,24

    float acc[8][4];
    #pragma unroll
    for (int j = 0; j < 8; ++j)
        #pragma unroll
        for (int q = 0; q < 4; ++q) acc[j][q] = 0.f;

    float4 xa[4];
    float  wv[8];
    {   // prefetch k-tile 0
        const float* xp = X + (size_t)(mb + arg) * KDIM + akb;
        #pragma unroll
        for (int p = 0; p < 4; ++p) xa[p] = *(const float4*)(xp + (size_t)p * 32 * KDIM);
        #pragma unroll
        for (int i = 0; i < 8; ++i) wv[i] = W[(size_t)(bkg + i) * EDIM + bn];
    }

    #pragma unroll 1
    for (int kt = 0; kt < NKT; ++kt) {
        // ---- store prefetched tile to smem ----
        #pragma unroll
        for (int p = 0; p < 4; ++p)
            *(float4*)&As[(arg + 32 * p) * AST + akb] = xa[p];
        #pragma unroll
        for (int i = 0; i < 8; ++i)
            Bs[bn * BST + bkg + i] = wv[i];
        __syncthreads();

        // ---- prefetch next k-tile ----
        if (kt + 1 < NKT) {
            const float* xp = X + (size_t)(mb + arg) * KDIM + (kt + 1) * BK + akb;
            #pragma unroll
            for (int p = 0; p < 4; ++p) xa[p] = *(const float4*)(xp + (size_t)p * 32 * KDIM);
            #pragma unroll
            for (int i = 0; i < 8; ++i)
                wv[i] = W[(size_t)((kt + 1) * BK + bkg + i) * EDIM + bn];
        }

        // ---- compute: 4 k-chunks, each: load+split all frags, then 24 MMAs ----
        #pragma unroll
        for (int kc = 0; kc < 4; ++kc) {
            const float* pa = As + (arow + g) * AST + (kc << 3) + c;
            float av0 = pa[0];
            float av1 = pa[8 * AST];
            float av2 = pa[4];
            float av3 = pa[8 * AST + 4];
            float bh[8][2], bl[8][2];
            #pragma unroll
            for (int j = 0; j < 8; ++j) {
                const float* pb = Bs + ((j << 3) + g) * BST + (kc << 3) + c;
                float bv0 = pb[0];
                float bv1 = pb[4];
                bh[j][0] = tf32r(bv0); bh[j][1] = tf32r(bv1);
                bl[j][0] = tf32r(bv0 - bh[j][0]); bl[j][1] = tf32r(bv1 - bh[j][1]);
            }
            float ah0 = tf32r(av0), ah1 = tf32r(av1), ah2 = tf32r(av2), ah3 = tf32r(av3);
            float al0 = tf32r(av0 - ah0), al1 = tf32r(av1 - ah1);
            float al2 = tf32r(av2 - ah2), al3 = tf32r(av3 - ah3);
            #pragma unroll
            for (int j = 0; j < 8; ++j) {
                mma_tf32(acc[j], ah0, ah1, ah2, ah3, bh[j][0], bh[j][1]);  // hi*hi
                mma_tf32(acc[j], al0, al1, al2, al3, bh[j][0], bh[j][1]);  // lo*hi
                mma_tf32(acc[j], ah0, ah1, ah2, ah3, bl[j][0], bl[j][1]);  // hi*lo
            }
        }
        __syncthreads();
    }

    // ---- epilogue: bias + ReLU -> scores smem ----
    #pragma unroll
    for (int j = 0; j < 8; ++j) {
        const int c0 = (j << 3) + t2;
        const int r0 = arow + g;
        const float b0v = bias[c0], b1v = bias[c0 + 1];
        float s0 = fmaxf(acc[j][0] + b0v, 0.f);
        float s1 = fmaxf(acc[j][1] + b1v, 0.f);
        float s2 = fmaxf(acc[j][2] + b0v, 0.f);
        float s3 = fmaxf(acc[j][3] + b1v, 0.f);
        sc[r0 * SCST + c0]           = s0;
        sc[r0 * SCST + c0 + 1]       = s1;
        sc[(r0 + 8) * SCST + c0]     = s2;
        sc[(r0 + 8) * SCST + c0 + 1] = s3;
    }
    __syncthreads();

    // ---- top-8 selection + masked softmax: one warp per token ----
    float* maskp = out + (size_t)TOKENS * EDIM;
    for (int r = arow; r < arow + 16; ++r) {
        float v0 = sc[r * SCST + lane];
        float v1 = sc[r * SCST + lane + 32];
        bool s0 = false, s1 = false;
        float m = 0.f;
        #pragma unroll
        for (int it = 0; it < TOPK; ++it) {
            float bv = s0 ? -1.f : v0;   // scores >= 0, so -1 never wins
            int   bi = s0 ? (1 << 20) : lane;
            if (!s1 && v1 > bv) { bv = v1; bi = lane + 32; }
            #pragma unroll
            for (int off = 16; off; off >>= 1) {
                float ov = __shfl_xor_sync(0xffffffffu, bv, off);
                int   oi = __shfl_xor_sync(0xffffffffu, bi, off);
                if (ov > bv || (ov == bv && oi < bi)) { bv = ov; bi = oi; }
            }
            if (it == 0) m = bv;                 // max of selected set
            if (bi == lane)            s0 = true;
            else if (bi == lane + 32)  s1 = true;
        }
        float e0 = s0 ? expf(v0 - m) : 0.f;
        float e1 = s1 ? expf(v1 - m) : 0.f;
        float sum = e0 + e1;
        #pragma unroll
        for (int off = 16; off; off >>= 1) sum += __shfl_xor_sync(0xffffffffu, sum, off);
        const float inv = 1.f / sum;
        const size_t gt = (size_t)(mb + r) * EDIM;
        out[gt + lane]        = e0 * inv;
        out[gt + lane + 32]   = e1 * inv;
        maskp[gt + lane]      = s0 ? 1.f : 0.f;
        maskp[gt + lane + 32] = s1 ? 1.f : 0.f;
    }
}

extern "C" void kernel_launch(void* const* d_in, const int* in_sizes, int n_in,
                              void* d_out, int out_size) {
    const float* X    = (const float*)d_in[0];
    const float* W    = (const float*)d_in[1];
    const float* bias = (const float*)d_in[2];
    float* out = (float*)d_out;

    router_kernel<<<TOKENS / BM, 256, SMEM_BYTES>>>(X, W, bias, out);
}

// round 6
// speedup vs baseline: 1.5360x; 1.5360x over previous
#include <cuda_runtime.h>
#include <cuda_fp16.h>
#include <stdint.h>

#define TOKENS 16384
#define KDIM   2048
#define EDIM   64
#define TOPK   8
#define BM     64
#define BK     32
#define NKT    (KDIM / BK)     // 64 k-tiles
#define SCST   66
#define WSCALE 1024.0f
#define WINV   (1.0f / 1024.0f)

// smem: Ahi[64*64B)@0, Alo@4096, Bhi@8192, Blo@12288 (16KB staging)
// epilogue alias: scores 64*66*4 = 16896B ; bias @16896 (256B)
#define SMEM_BYTES 17280

__device__ __forceinline__ uint32_t pack2h(__half a, __half b) {
    return (uint32_t)__half_as_ushort(a) | ((uint32_t)__half_as_ushort(b) << 16);
}

__device__ __forceinline__ void mma_f16(float c[4],
                                        uint32_t a0, uint32_t a1, uint32_t a2, uint32_t a3,
                                        uint32_t b0, uint32_t b1) {
    asm volatile(
        "mma.sync.aligned.m16n8k16.row.col.f32.f16.f16.f32 "
        "{%0,%1,%2,%3},{%4,%5,%6,%7},{%8,%9},{%0,%1,%2,%3};\n"
        : "+f"(c[0]), "+f"(c[1]), "+f"(c[2]), "+f"(c[3])
        : "r"(a0), "r"(a1), "r"(a2), "r"(a3), "r"(b0), "r"(b1));
}

// split v into fp16 hi/lo
__device__ __forceinline__ void split16(float v, __half& h, __half& l) {
    h = __float2half_rn(v);
    l = __float2half_rn(v - __half2float(h));
}

__global__ void __launch_bounds__(128, 2)
router_kernel(const float* __restrict__ X, const float* __restrict__ W,
              const float* __restrict__ bias, float* __restrict__ out)
{
    __shared__ char smem[SMEM_BYTES];
    char* Ahi = smem;           // row r: 64B (32 halves), word w at ((w)^s(r))*4
    char* Bhi = smem + 8192;    // Bt[n][k], same swizzle
    float* sc  = (float*)smem;  // epilogue alias
    float* bsh = (float*)(smem + 16896);

    const int tid  = threadIdx.x;
    const int wrp  = tid >> 5;
    const int lane = tid & 31;
    const int mb   = blockIdx.x * BM;

    const int g  = lane >> 2;
    const int c  = lane & 3;
    const int s4 = ((g >> 1) & 3) << 2;     // per-lane swizzle code (rows g, g+8 share it)
    const int R0 = (wrp >> 1) << 5;          // warp row base (0/32)
    const int N0 = (wrp & 1) << 5;           // warp col base (0/32)

    if (tid < EDIM) bsh[tid] = bias[tid];

    // staging decomposition (128 threads)
    const int ar  = tid >> 1;                // A row 0..63
    const int akw = (tid & 1) << 3;          // A word base 0/8 (16 halves each)
    const int asw = ((ar >> 1) & 3) << 2;    // A row swizzle
    const int bn  = tid & 63;                // B expert 0..63
    const int bkq = tid >> 6;                // B k-quarter 0/1
    const int bkw = bkq << 3;
    const int bsw = ((bn >> 1) & 3) << 2;

    float acc[2][4][4];
    #pragma unroll
    for (int mt = 0; mt < 2; ++mt)
        #pragma unroll
        for (int j = 0; j < 4; ++j)
            #pragma unroll
            for (int q = 0; q < 4; ++q) acc[mt][j][q] = 0.f;

    float4 xa[4];
    float  wv[16];
    {   // prefetch tile 0
        const float* xp = X + (size_t)(mb + ar) * KDIM + (akw << 1);
        #pragma unroll
        for (int p = 0; p < 4; ++p) xa[p] = *(const float4*)(xp + 4 * p);
        const float* wp = W + (size_t)(bkq * 16) * EDIM + bn;
        #pragma unroll
        for (int i = 0; i < 16; ++i) wv[i] = wp[(size_t)i * EDIM];
    }

    #pragma unroll 1
    for (int kt = 0; kt < NKT; ++kt) {
        if (kt) __syncthreads();   // consumers done with smem

        // ---- store staged tile (fp16 hi/lo split), swizzled ----
        {
            float v[16] = {xa[0].x, xa[0].y, xa[0].z, xa[0].w,
                           xa[1].x, xa[1].y, xa[1].z, xa[1].w,
                           xa[2].x, xa[2].y, xa[2].z, xa[2].w,
                           xa[3].x, xa[3].y, xa[3].z, xa[3].w};
            uint32_t ph[8], pl[8];
            #pragma unroll
            for (int i = 0; i < 8; ++i) {
                __half h0, l0, h1, l1;
                split16(v[2 * i],     h0, l0);
                split16(v[2 * i + 1], h1, l1);
                ph[i] = pack2h(h0, h1);
                pl[i] = pack2h(l0, l1);
            }
            char* pa = Ahi + ar * 64;
            const int o0 = ((akw)     ^ asw) << 2;
            const int o1 = ((akw + 4) ^ asw) << 2;
            *(uint4*)(pa + o0)        = make_uint4(ph[0], ph[1], ph[2], ph[3]);
            *(uint4*)(pa + o1)        = make_uint4(ph[4], ph[5], ph[6], ph[7]);
            *(uint4*)(pa + 4096 + o0) = make_uint4(pl[0], pl[1], pl[2], pl[3]);
            *(uint4*)(pa + 4096 + o1) = make_uint4(pl[4], pl[5], pl[6], pl[7]);
        }
        {
            uint32_t ph[8], pl[8];
            #pragma unroll
            for (int i = 0; i < 8; ++i) {
                __half h0, l0, h1, l1;
                split16(wv[2 * i]     * WSCALE, h0, l0);
                split16(wv[2 * i + 1] * WSCALE, h1, l1);
                ph[i] = pack2h(h0, h1);
                pl[i] = pack2h(l0, l1);
            }
            char* pb = Bhi + bn * 64;
            const int o0 = ((bkw)     ^ bsw) << 2;
            const int o1 = ((bkw + 4) ^ bsw) << 2;
            *(uint4*)(pb + o0)        = make_uint4(ph[0], ph[1], ph[2], ph[3]);
            *(uint4*)(pb + o1)        = make_uint4(ph[4], ph[5], ph[6], ph[7]);
            *(uint4*)(pb + 4096 + o0) = make_uint4(pl[0], pl[1], pl[2], pl[3]);
            *(uint4*)(pb + 4096 + o1) = make_uint4(pl[4], pl[5], pl[6], pl[7]);
        }
        __syncthreads();

        // ---- prefetch next tile ----
        if (kt + 1 < NKT) {
            const float* xp = X + (size_t)(mb + ar) * KDIM + (kt + 1) * BK + (akw << 1);
            #pragma unroll
            for (int p = 0; p < 4; ++p) xa[p] = *(const float4*)(xp + 4 * p);
            const float* wp = W + (size_t)((kt + 1) * BK + bkq * 16) * EDIM + bn;
            #pragma unroll
            for (int i = 0; i < 16; ++i) wv[i] = wp[(size_t)i * EDIM];
        }

        // ---- compute: 2 k-chunks x (2 m-tiles x 4 n-subtiles) x 3 products ----
        #pragma unroll
        for (int kc = 0; kc < 2; ++kc) {
            const int o0 = ((kc * 8 + c)     ^ s4) << 2;
            const int o1 = ((kc * 8 + c + 4) ^ s4) << 2;
            uint32_t ah[2][4], al[2][4];
            #pragma unroll
            for (int mt = 0; mt < 2; ++mt) {
                const char* pa = Ahi + (R0 + mt * 16 + g) * 64;
                ah[mt][0] = *(const uint32_t*)(pa + o0);
                ah[mt][1] = *(const uint32_t*)(pa + 512 + o0);
                ah[mt][2] = *(const uint32_t*)(pa + o1);
                ah[mt][3] = *(const uint32_t*)(pa + 512 + o1);
                al[mt][0] = *(const uint32_t*)(pa + 4096 + o0);
                al[mt][1] = *(const uint32_t*)(pa + 4608 + o0);
                al[mt][2] = *(const uint32_t*)(pa + 4096 + o1);
                al[mt][3] = *(const uint32_t*)(pa + 4608 + o1);
            }
            #pragma unroll
            for (int j = 0; j < 4; ++j) {
                const char* pb = Bhi + (N0 + j * 8 + g) * 64;
                uint32_t bh0 = *(const uint32_t*)(pb + o0);
                uint32_t bh1 = *(const uint32_t*)(pb + o1);
                uint32_t bl0 = *(const uint32_t*)(pb + 4096 + o0);
                uint32_t bl1 = *(const uint32_t*)(pb + 4096 + o1);
                #pragma unroll
                for (int mt = 0; mt < 2; ++mt) {
                    mma_f16(acc[mt][j], ah[mt][0], ah[mt][1], ah[mt][2], ah[mt][3], bh0, bh1);
                    mma_f16(acc[mt][j], al[mt][0], al[mt][1], al[mt][2], al[mt][3], bh0, bh1);
                    mma_f16(acc[mt][j], ah[mt][0], ah[mt][1], ah[mt][2], ah[mt][3], bl0, bl1);
                }
            }
        }
    }
    __syncthreads();   // staging smem -> scores alias

    // ---- epilogue: unscale + bias + ReLU -> scores smem ----
    #pragma unroll
    for (int mt = 0; mt < 2; ++mt)
        #pragma unroll
        for (int j = 0; j < 4; ++j) {
            const int col = N0 + j * 8 + 2 * c;
            const int r0  = R0 + mt * 16 + g;
            const float b0v = bsh[col], b1v = bsh[col + 1];
            sc[r0 * SCST + col]           = fmaxf(acc[mt][j][0] * WINV + b0v, 0.f);
            sc[r0 * SCST + col + 1]       = fmaxf(acc[mt][j][1] * WINV + b1v, 0.f);
            sc[(r0 + 8) * SCST + col]     = fmaxf(acc[mt][j][2] * WINV + b0v, 0.f);
            sc[(r0 + 8) * SCST + col + 1] = fmaxf(acc[mt][j][3] * WINV + b1v, 0.f);
        }
    __syncthreads();

    // ---- top-8 selection + masked softmax: one warp per token ----
    float* maskp = out + (size_t)TOKENS * EDIM;
    const int arow = wrp << 4;
    for (int r = arow; r < arow + 16; ++r) {
        float v0 = sc[r * SCST + lane];
        float v1 = sc[r * SCST + lane + 32];
        bool sel0 = false, sel1 = false;
        float m = 0.f;
        #pragma unroll
        for (int it = 0; it < TOPK; ++it) {
            float bv = sel0 ? -1.f : v0;   // scores >= 0, -1 never wins
            int   bi = sel0 ? (1 << 20) : lane;
            if (!sel1 && v1 > bv) { bv = v1; bi = lane + 32; }
            #pragma unroll
            for (int off = 16; off; off >>= 1) {
                float ov = __shfl_xor_sync(0xffffffffu, bv, off);
                int   oi = __shfl_xor_sync(0xffffffffu, bi, off);
                if (ov > bv || (ov == bv && oi < bi)) { bv = ov; bi = oi; }
            }
            if (it == 0) m = bv;
            if (bi == lane)           sel0 = true;
            else if (bi == lane + 32) sel1 = true;
        }
        float e0 = sel0 ? expf(v0 - m) : 0.f;
        float e1 = sel1 ? expf(v1 - m) : 0.f;
        float sum = e0 + e1;
        #pragma unroll
        for (int off = 16; off; off >>= 1) sum += __shfl_xor_sync(0xffffffffu, sum, off);
        const float inv = 1.f / sum;
        const size_t gt = (size_t)(mb + r) * EDIM;
        out[gt + lane]        = e0 * inv;
        out[gt + lane + 32]   = e1 * inv;
        maskp[gt + lane]      = sel0 ? 1.f : 0.f;
        maskp[gt + lane + 32] = sel1 ? 1.f : 0.f;
    }
}

extern "C" void kernel_launch(void* const* d_in, const int* in_sizes, int n_in,
                              void* d_out, int out_size) {
    const float* X    = (const float*)d_in[0];
    const float* W    = (const float*)d_in[1];
    const float* bias = (const float*)d_in[2];
    float* out = (float*)d_out;

    router_kernel<<<TOKENS / BM, 128>>>(X, W, bias, out);
}